// round 15
// baseline (speedup 1.0000x reference)
#include <cuda_runtime.h>
#include <cuda_bf16.h>
#include <math.h>
#include <cstdint>

// Problem constants
#define BB   4
#define NN   16384
#define MM   (BB * NN)        // 65536 points total
#define HID  128
#define RESO 128
#define R2   (RESO * RESO)
#define NBLK 5
#define LDXH 384              // plane row: [H(128) | net/x(256)] bf16 per plane

// Weight plane offsets (element index into g_wh/g_wl)
#define WOFF_FC0(k)  ((size_t)(k) * 32768)
#define WOFF_WCAT(k) (163840 + (size_t)(k) * 49152)
#define WOFF_FCC     409600
#define WTOTAL       425984

// GEMM smem stage: A 16384 B (2 bf16 planes 8192 each, or u32 bins layout)
//                + W hi/lo pitch-20 (2 x 10240 B)
#define STG 36864

// ---------------------------------------------------------------------------
// Scratch
// ---------------------------------------------------------------------------
__device__ int           g_idx[MM];
__device__ __nv_bfloat16 g_Xh[(size_t)MM * LDXH];          // 50.3 MB
__device__ __nv_bfloat16 g_Xl[(size_t)MM * LDXH];          // 50.3 MB
__device__ unsigned      g_bins0[(size_t)BB * R2 * HID];   // 33.5 MB
__device__ unsigned      g_bins1[(size_t)BB * R2 * HID];   // 33.5 MB
__device__ float         g_cnt[BB * R2];
__device__ __nv_bfloat16 g_wh[WTOTAL];
__device__ __nv_bfloat16 g_wl[WTOTAL];

// ---------------------------------------------------------------------------
// Helpers
// ---------------------------------------------------------------------------
__device__ __forceinline__ uint32_t smem_u32(const void* p) {
    uint32_t a;
    asm("{ .reg .u64 t; cvta.to.shared.u64 t, %1; cvt.u32.u64 %0, t; }"
        : "=r"(a) : "l"(p));
    return a;
}
__device__ __forceinline__ uint32_t prmt(uint32_t a, uint32_t b, uint32_t c) {
    uint32_t d;
    asm("prmt.b32 %0, %1, %2, %3;" : "=r"(d) : "r"(a), "r"(b), "r"(c));
    return d;
}
__device__ __forceinline__ unsigned f_enc(float x) {
    unsigned u = __float_as_uint(x);
    return (u & 0x80000000u) ? ~u : (u | 0x80000000u);
}
__device__ __forceinline__ float f_dec(unsigned u) {
    return (u & 0x80000000u) ? __uint_as_float(u & 0x7FFFFFFFu) : __uint_as_float(~u);
}
__device__ __forceinline__ float cvtB(uint32_t u, bool relu) {
    if (relu) return (u > 0x80000000u) ? __uint_as_float(u & 0x7FFFFFFFu) : 0.f;
    return f_dec(u);
}
// fast hi/lo split of a pair of f32 into two packed bf16x2 regs (elem a = low)
__device__ __forceinline__ void fsplit2(float a, float b, uint32_t& hp, uint32_t& lp) {
    asm("cvt.rn.bf16x2.f32 %0, %1, %2;" : "=r"(hp) : "f"(b), "f"(a));
    float ah = __uint_as_float(hp << 16);
    float bh = __uint_as_float(hp & 0xFFFF0000u);
    float ra = a - ah, rb = b - bh;
    asm("cvt.rn.bf16x2.f32 %0, %1, %2;" : "=r"(lp) : "f"(rb), "f"(ra));
}
// ldmatrix x4 (non-trans)
__device__ __forceinline__ void ldsm_x4(uint32_t& r0, uint32_t& r1,
                                        uint32_t& r2, uint32_t& r3, uint32_t addr) {
    asm volatile("ldmatrix.sync.aligned.m8n8.x4.shared.b16 {%0,%1,%2,%3}, [%4];"
                 : "=r"(r0), "=r"(r1), "=r"(r2), "=r"(r3) : "r"(addr));
}

// mma.sync m16n8k16 bf16 -> f32 accumulate
__device__ __forceinline__ void mma16816(float* d, const uint32_t* a,
                                         uint32_t b0, uint32_t b1) {
    asm volatile(
        "mma.sync.aligned.m16n8k16.row.col.f32.bf16.bf16.f32 "
        "{%0,%1,%2,%3}, {%4,%5,%6,%7}, {%8,%9}, {%0,%1,%2,%3};"
        : "+f"(d[0]), "+f"(d[1]), "+f"(d[2]), "+f"(d[3])
        : "r"(a[0]), "r"(a[1]), "r"(a[2]), "r"(a[3]), "r"(b0), "r"(b1));
}

// ---------------------------------------------------------------------------
// Weight prep
// ---------------------------------------------------------------------------
__global__ void k_wprep(const float* __restrict__ fc0,
                        const float* __restrict__ w1,
                        const float* __restrict__ ws,
                        const float* __restrict__ fcc) {
    int t = blockIdx.x * blockDim.x + threadIdx.x;
    if (t >= WTOTAL) return;
    float v;
    if (t < 163840) {
        v = fc0[t];
    } else if (t < 409600) {
        int u = t - 163840;
        int k = u / 49152, r = u % 49152;
        int n = r / 384, c = r % 384;
        if (c < 128) v = w1[((size_t)k * HID + n) * 128 + c];
        else         v = ws[((size_t)k * HID + n) * 256 + (c - 128)];
    } else {
        v = fcc[t - 409600];
    }
    __nv_bfloat16 hi = __float2bfloat16(v);
    float lo = v - __bfloat162float(hi);
    g_wh[t] = hi;
    g_wl[t] = __float2bfloat16(lo);
}

// ---------------------------------------------------------------------------
// Zeroing
// ---------------------------------------------------------------------------
__global__ void k_zero_all() {
    int t = blockIdx.x * blockDim.x + threadIdx.x;
    uint4 z = make_uint4(0, 0, 0, 0);
    ((uint4*)g_bins0)[t] = z;
    ((uint4*)g_bins1)[t] = z;
    if (t < (BB * R2) / 4) ((uint4*)g_cnt)[t] = z;
}
__global__ void k_zero_b(unsigned* __restrict__ p) {
    int t = blockIdx.x * blockDim.x + threadIdx.x;
    ((uint4*)p)[t] = make_uint4(0, 0, 0, 0);
}

// ---------------------------------------------------------------------------
// fc_pos + bin index + bin counts (writes split planes)
// ---------------------------------------------------------------------------
__global__ void k_pos(const float* __restrict__ pts,
                      const float* __restrict__ w,
                      const float* __restrict__ b) {
    int m = blockIdx.x;
    int j = threadIdx.x;
    float p0 = pts[(size_t)m * 3 + 0];
    float p1 = pts[(size_t)m * 3 + 1];
    float p2 = pts[(size_t)m * 3 + 2];
    float v = b[j] + p0 * w[j * 3 + 0] + p1 * w[j * 3 + 1] + p2 * w[j * 3 + 2];
    __nv_bfloat16 h = __float2bfloat16(v);
    __nv_bfloat16 l = __float2bfloat16(v - __bfloat162float(h));
    g_Xh[(size_t)m * LDXH + 128 + j] = h;
    g_Xl[(size_t)m * LDXH + 128 + j] = l;
    if (j == 0) {
        int gx = (int)(p0 * (float)RESO);
        int gy = (int)(p1 * (float)RESO);
        gx = min(max(gx, 0), RESO - 1);
        gy = min(max(gy, 0), RESO - 1);
        int idx = gx + RESO * gy;
        g_idx[m] = idx;
        atomicAdd(&g_cnt[((m >> 14) << 14) + idx], 1.0f);
    }
}

// ---------------------------------------------------------------------------
// Fused pipelined mma.sync GEMM: C[128 x 128] per CTA = act(A) @ W^T + bias
// 8 warps (4 M x 2 N), BK=32, 3-stage cp.async pipeline, ONE barrier/chunk.
// XH chunks: two bf16 smem planes, A fragments via ldmatrix.x4.
// Bins chunks: u32 f_enc layout, decode + fsplit2 (as before).
// W fragments via ldmatrix.x4 (both planes).
//  mode 0: write relu split -> planes col c_col0
//  mode 1: write raw split -> planes; if binsDst scatter atomicMax(enc)
//  mode 2: scatter atomicAdd C+bias into (float*)binsDst
// ---------------------------------------------------------------------------
__global__ void __launch_bounds__(256, 2) k_gemm_mma(
    int a_col0, size_t woff, int K, int reluAll,
    const float* __restrict__ bias, int c_col0, int mode,
    const unsigned* __restrict__ binsSrc, unsigned* __restrict__ binsDst,
    int nXHc)
{
    extern __shared__ char dsm[];
    uint32_t sbase = smem_u32(dsm);
    float* bias_s = (float*)(dsm + 3 * STG);

    int tid = threadIdx.x;
    int wid = tid >> 5;
    int lid = tid & 31;
    int m0  = blockIdx.x * 128;
    int batch = m0 >> 14;
    int warp_m = wid & 3;
    int warp_n = wid >> 2;
    int g  = lid >> 2;
    int tg = lid & 3;
    int swz = (g & 3) << 3;          // bins-path A read swizzle (u32 units)

    // W ldmatrix lane mapping (validated)
    int rip  = (lid & 7) + ((lid >> 4) << 3);
    int ksel = (lid >> 3) & 1;
    uint32_t wfrag_off = 16384 + (uint32_t)(warp_n * 64 + rip) * 80 + ksel * 16;

    // A ldmatrix lane mapping: rowA covers m16 (rows 0..15 of warp tile)
    int rowA = (warp_m << 5) + (lid & 7) + (((lid >> 3) & 1) << 3);
    int s3   = (rowA >> 1) & 3;      // plane swizzle selector (const per lane)
    int kblk = lid >> 4;             // 0/1 -> k0 / k0+8
    uint32_t afrag_off = (uint32_t)rowA * 64;

    if (tid < 128) bias_s[tid] = bias[tid];

    // ---- Producer sources ----
    // XH plane path: 4 segs/thread: i>>1 = plane, i&1 = +64 rows
    const char* baseXh = (const char*)(g_Xh + (size_t)(m0 + (tid >> 2)) * LDXH
                                       + a_col0 + (tid & 3) * 8);
    const char* baseXl = (const char*)(g_Xl + (size_t)(m0 + (tid >> 2)) * LDXH
                                       + a_col0 + (tid & 3) * 8);
    uint32_t sAp[4];
    {
        #pragma unroll
        for (int i = 0; i < 4; i++) {
            int lrow = ((i & 1) << 6) + (tid >> 2);
            sAp[i] = ((i >> 1) * 8192) + lrow * 64
                   + (((tid & 3) ^ ((lrow >> 1) & 3)) << 4);
        }
    }
    // bins u32 path: old layout
    uint64_t gAb[4];
    uint32_t sAb[4];
    if (binsSrc) {
        #pragma unroll
        for (int i = 0; i < 4; i++) {
            int row = (i << 5) + (tid >> 3);
            int seg = tid & 7;
            int bi = g_idx[m0 + row];
            gAb[i] = (uint64_t)(binsSrc + (((size_t)(batch << 14) + bi) << 7) + seg * 4);
            sAb[i] = row * 128 + ((seg * 16) ^ ((row & 3) << 5));
        }
    }
    // W
    uint64_t gW[4];
    uint32_t sW[4];
    {
        #pragma unroll
        for (int i = 0; i < 4; i++) {
            int idx = tid + (i << 8);
            int pl = idx >> 9, rem = idx & 511;
            int row = rem >> 2, seg = rem & 3;
            const __nv_bfloat16* gp = pl ? g_wl : g_wh;
            gW[i] = (uint64_t)(gp + woff + (size_t)row * K + seg * 8);
            sW[i] = 16384 + pl * 10240 + row * 80 + seg * 16;
        }
    }

    auto issue = [&](int c, int s) {
        uint32_t sb = sbase + s * STG;
        if (c < nXHc) {
            uint64_t adv = (uint64_t)(c << 6);                  // 32 bf16 = 64 B
            const char* s0 = baseXh + adv;
            const char* s1 = baseXh + (size_t)64 * LDXH * 2 + adv;
            const char* s2 = baseXl + adv;
            const char* s3p = baseXl + (size_t)64 * LDXH * 2 + adv;
            asm volatile("cp.async.cg.shared.global [%0], [%1], 16;"
                         :: "r"(sb + sAp[0]), "l"(s0) : "memory");
            asm volatile("cp.async.cg.shared.global [%0], [%1], 16;"
                         :: "r"(sb + sAp[1]), "l"(s1) : "memory");
            asm volatile("cp.async.cg.shared.global [%0], [%1], 16;"
                         :: "r"(sb + sAp[2]), "l"(s2) : "memory");
            asm volatile("cp.async.cg.shared.global [%0], [%1], 16;"
                         :: "r"(sb + sAp[3]), "l"(s3p) : "memory");
        } else {
            uint64_t adv = (uint64_t)((c - nXHc) << 7);         // 32 u32 = 128 B
            #pragma unroll
            for (int i = 0; i < 4; i++)
                asm volatile("cp.async.cg.shared.global [%0], [%1], 16;"
                             :: "r"(sb + sAb[i]), "l"(gAb[i] + adv) : "memory");
        }
        uint64_t advW = (uint64_t)(c << 6);
        #pragma unroll
        for (int i = 0; i < 4; i++)
            asm volatile("cp.async.cg.shared.global [%0], [%1], 16;"
                         :: "r"(sb + sW[i]), "l"(gW[i] + advW) : "memory");
        asm volatile("cp.async.commit_group;" ::: "memory");
    };

    float acc[2][8][4];
    #pragma unroll
    for (int mt = 0; mt < 2; mt++)
        #pragma unroll
        for (int nt = 0; nt < 8; nt++)
            #pragma unroll
            for (int r = 0; r < 4; r++) acc[mt][nt][r] = 0.f;

    const int nchunks = K >> 5;
    issue(0, 0);
    issue(1, 1);

    int s = 0;
    for (int c = 0; c < nchunks; c++) {
        if (c + 1 < nchunks) {
            asm volatile("cp.async.wait_group 1;" ::: "memory");
        } else {
            asm volatile("cp.async.wait_group 0;" ::: "memory");
        }
        __syncthreads();
        if (c + 2 < nchunks) {
            int s2 = s + 2; if (s2 >= 3) s2 -= 3;
            issue(c + 2, s2);
        }

        uint32_t stg_b = sbase + s * STG;
        const uint32_t* Au = (const uint32_t*)(dsm + s * STG);
        uint32_t wmb = stg_b + wfrag_off;
        uint32_t amb = stg_b + afrag_off;
        bool enc  = (c >= nXHc);
        bool relu = (reluAll != 0);

        #pragma unroll
        for (int ks = 0; ks < 2; ks++) {
            uint32_t ah[2][4], al[2][4];
            if (!enc) {
                #pragma unroll
                for (int mt = 0; mt < 2; mt++) {
                    uint32_t adr = amb + mt * 1024
                                 + (uint32_t)((((ks << 1) | kblk) ^ s3) << 4);
                    ldsm_x4(ah[mt][0], ah[mt][1], ah[mt][2], ah[mt][3], adr);
                    ldsm_x4(al[mt][0], al[mt][1], al[mt][2], al[mt][3], adr + 8192);
                    if (relu) {
                        #pragma unroll
                        for (int r = 0; r < 4; r++) {
                            uint32_t msk = prmt(ah[mt][r], ah[mt][r], 0xBB99);
                            ah[mt][r] &= ~msk;
                            al[mt][r] &= ~msk;
                        }
                    }
                }
            } else {
                int col0 = (ks << 4) + (tg << 1);
                #pragma unroll
                for (int mt = 0; mt < 2; mt++) {
                    int r0 = (warp_m << 5) + (mt << 4) + g;
                    uint2 u0 = *(const uint2*)(Au + (r0 << 5) + (col0 ^ swz));
                    uint2 u1 = *(const uint2*)(Au + ((r0 + 8) << 5) + (col0 ^ swz));
                    uint2 u2 = *(const uint2*)(Au + (r0 << 5) + ((col0 + 8) ^ swz));
                    uint2 u3 = *(const uint2*)(Au + ((r0 + 8) << 5) + ((col0 + 8) ^ swz));
                    fsplit2(cvtB(u0.x, relu), cvtB(u0.y, relu), ah[mt][0], al[mt][0]);
                    fsplit2(cvtB(u1.x, relu), cvtB(u1.y, relu), ah[mt][1], al[mt][1]);
                    fsplit2(cvtB(u2.x, relu), cvtB(u2.y, relu), ah[mt][2], al[mt][2]);
                    fsplit2(cvtB(u3.x, relu), cvtB(u3.y, relu), ah[mt][3], al[mt][3]);
                }
            }
            #pragma unroll
            for (int p = 0; p < 4; p++) {
                uint32_t adr = wmb + p * 1280 + (ks << 5);
                uint32_t bh0a, bh1a, bh0b, bh1b, bl0a, bl1a, bl0b, bl1b;
                ldsm_x4(bh0a, bh1a, bh0b, bh1b, adr);
                ldsm_x4(bl0a, bl1a, bl0b, bl1b, adr + 10240);
                #pragma unroll
                for (int mt = 0; mt < 2; mt++) {
                    mma16816(acc[mt][2 * p], ah[mt], bh0a, bh1a);
                    mma16816(acc[mt][2 * p], ah[mt], bl0a, bl1a);
                    mma16816(acc[mt][2 * p], al[mt], bh0a, bh1a);
                    mma16816(acc[mt][2 * p + 1], ah[mt], bh0b, bh1b);
                    mma16816(acc[mt][2 * p + 1], ah[mt], bl0b, bl1b);
                    mma16816(acc[mt][2 * p + 1], al[mt], bh0b, bh1b);
                }
            }
        }
        if (++s >= 3) s -= 3;
    }

    // Epilogue rows: r_base + {0,8,16,24}
    int r_base = m0 + (warp_m << 5) + g;
    size_t bofs[4];
    if ((mode == 1 && binsDst) || mode == 2) {
        #pragma unroll
        for (int j = 0; j < 4; j++) {
            int bi = g_idx[r_base + 8 * j];
            bofs[j] = ((size_t)(batch << 14) + bi) << 7;
        }
    }

    #pragma unroll
    for (int mt = 0; mt < 2; mt++) {
        int row0 = r_base + (mt << 4);
        #pragma unroll
        for (int nt = 0; nt < 8; nt++) {
            int colL = (warp_n << 6) + (nt << 3) + (tg << 1);
            float b0 = bias_s[colL], b1 = bias_s[colL + 1];
            float v0 = acc[mt][nt][0] + b0, v1 = acc[mt][nt][1] + b1;  // row0
            float v2 = acc[mt][nt][2] + b0, v3 = acc[mt][nt][3] + b1;  // row0+8
            if (mode == 0) {
                v0 = fmaxf(v0, 0.f); v1 = fmaxf(v1, 0.f);
                v2 = fmaxf(v2, 0.f); v3 = fmaxf(v3, 0.f);
            }
            if (mode == 2) {
                float* sums = (float*)binsDst;
                atomicAdd(&sums[bofs[mt * 2 + 0] + colL],     v0);
                atomicAdd(&sums[bofs[mt * 2 + 0] + colL + 1], v1);
                atomicAdd(&sums[bofs[mt * 2 + 1] + colL],     v2);
                atomicAdd(&sums[bofs[mt * 2 + 1] + colL + 1], v3);
            } else {
                uint32_t hp, lp;
                size_t o0 = (size_t)row0 * LDXH + c_col0 + colL;
                size_t o1 = (size_t)(row0 + 8) * LDXH + c_col0 + colL;
                fsplit2(v0, v1, hp, lp);
                *(uint32_t*)(g_Xh + o0) = hp;
                *(uint32_t*)(g_Xl + o0) = lp;
                fsplit2(v2, v3, hp, lp);
                *(uint32_t*)(g_Xh + o1) = hp;
                *(uint32_t*)(g_Xl + o1) = lp;
                if (mode == 1 && binsDst) {
                    atomicMax(&binsDst[bofs[mt * 2 + 0] + colL],     f_enc(v0));
                    atomicMax(&binsDst[bofs[mt * 2 + 0] + colL + 1], f_enc(v1));
                    atomicMax(&binsDst[bofs[mt * 2 + 1] + colL],     f_enc(v2));
                    atomicMax(&binsDst[bofs[mt * 2 + 1] + colL + 1], f_enc(v3));
                }
            }
        }
    }
}

// ---------------------------------------------------------------------------
// Final: mean + transposed plane write (sums = bins0 as float)
// ---------------------------------------------------------------------------
__global__ void k_final(float* __restrict__ out) {
    __shared__ float s[32][33];
    __shared__ float sc[32];
    int b    = blockIdx.z;
    int bin0 = blockIdx.x * 32;
    int c0   = blockIdx.y * 32;
    const float* sums = (const float*)g_bins0;

    #pragma unroll
    for (int i = 0; i < 4; i++) {
        int binl = threadIdx.y + i * 8;
        s[binl][threadIdx.x] =
            sums[((size_t)(b * R2 + bin0 + binl)) * HID + c0 + threadIdx.x];
    }
    if (threadIdx.y == 0)
        sc[threadIdx.x] = fmaxf(g_cnt[b * R2 + bin0 + threadIdx.x], 1.0f);
    __syncthreads();

    #pragma unroll
    for (int i = 0; i < 4; i++) {
        int c = c0 + threadIdx.y + i * 8;
        out[((size_t)(b * HID + c)) * R2 + bin0 + threadIdx.x] =
            s[threadIdx.x][threadIdx.y + i * 8] / sc[threadIdx.x];
    }
}

// ---------------------------------------------------------------------------
// Launch
// ---------------------------------------------------------------------------
extern "C" void kernel_launch(void* const* d_in, const int* in_sizes, int n_in,
                              void* d_out, int out_size) {
    const float* points    = (const float*)d_in[0];
    const float* fc_pos_w  = (const float*)d_in[1];
    const float* fc_pos_b  = (const float*)d_in[2];
    const float* blk_fc0_w = (const float*)d_in[3];
    const float* blk_fc0_b = (const float*)d_in[4];
    const float* blk_fc1_w = (const float*)d_in[5];
    const float* blk_fc1_b = (const float*)d_in[6];
    const float* blk_sc_w  = (const float*)d_in[7];
    const float* fc_c_w    = (const float*)d_in[8];
    const float* fc_c_b    = (const float*)d_in[9];
    float* out = (float*)d_out;

    const int GB      = MM / 128;       // 512 GEMM blocks
    const int SMEM_SZ = 3 * STG + 512;  // 111104 B

    cudaFuncSetAttribute(k_gemm_mma, cudaFuncAttributeMaxDynamicSharedMemorySize, SMEM_SZ);

    unsigned* bins[2];
    cudaGetSymbolAddress((void**)&bins[0], g_bins0);
    cudaGetSymbolAddress((void**)&bins[1], g_bins1);

    k_wprep<<<(WTOTAL + 255) / 256, 256>>>(blk_fc0_w, blk_fc1_w, blk_sc_w, fc_c_w);
    k_zero_all<<<8192, 256>>>();
    k_pos<<<MM, 256>>>(points, fc_pos_w, fc_pos_b);

    // Block 0: H = relu(relu(x)@W0+b0) -> col 0;
    // net = [reluH | x]@Wcat + b1 -> col 128, scatter-max -> bins0
    k_gemm_mma<<<GB, 256, SMEM_SZ>>>(128, WOFF_FC0(0), 256, 1, blk_fc0_b, 0, 0,
                                     nullptr, nullptr, 8);
    k_gemm_mma<<<GB, 256, SMEM_SZ>>>(0, WOFF_WCAT(0), 384, 0, blk_fc1_b, 128, 1,
                                     nullptr, bins[0], 12);

    // Blocks 1..4: gather pooled from src bins; GEMM2 scatters into dst bins
    for (int k = 1; k < NBLK; k++) {
        const unsigned* src = bins[(k + 1) & 1];
        unsigned* dst = (k < 4) ? bins[k & 1] : nullptr;
        k_gemm_mma<<<GB, 256, SMEM_SZ>>>(128, WOFF_FC0(k), 256, 1,
                                         blk_fc0_b + k * HID, 0, 0,
                                         src, nullptr, 4);
        k_gemm_mma<<<GB, 256, SMEM_SZ>>>(0, WOFF_WCAT(k), 384, 0,
                                         blk_fc1_b + k * HID, 128, 1,
                                         src, dst, 8);
        if (k == 1) k_zero_b<<<8192, 256>>>(bins[0]);
        if (k == 2) k_zero_b<<<8192, 256>>>(bins[1]);
        if (k == 3) k_zero_b<<<8192, 256>>>(bins[0]);   // becomes sums buffer
    }

    // fc_c: relu(net)@fcc + b -> scatter-add into sums (= bins0)
    k_gemm_mma<<<GB, 256, SMEM_SZ>>>(128, WOFF_FCC, 128, 1, fc_c_b, 0, 2,
                                     nullptr, bins[0], 4);

    dim3 fgrid(R2 / 32, HID / 32, BB);
    dim3 fblk(32, 8);
    k_final<<<fgrid, fblk>>>(out);
}

// round 17
// speedup vs baseline: 1.0504x; 1.0504x over previous
#include <cuda_runtime.h>
#include <cuda_bf16.h>
#include <math.h>
#include <cstdint>

// Problem constants
#define BB   4
#define NN   16384
#define MM   (BB * NN)        // 65536 points total
#define HID  128
#define RESO 128
#define R2   (RESO * RESO)
#define NBLK 5
#define LDXH 384              // row buffer: [H(128) | net/x(256)] packed-split u32

// Weight plane offsets (element index into g_wh/g_wl)
#define WOFF_FC0(k)  ((size_t)(k) * 32768)
#define WOFF_WCAT(k) (163840 + (size_t)(k) * 49152)
#define WOFF_FCC     409600
#define WTOTAL       425984

// GEMM smem stage: A u32 128x32 swizzled (16384 B) + W hi/lo pitch-20 (20480 B)
#define STG 36864

// ---------------------------------------------------------------------------
// Scratch
// ---------------------------------------------------------------------------
__device__ int           g_idx[MM];
__device__ unsigned      g_XH[(size_t)MM * LDXH];          // ~100 MB, packed split
__device__ unsigned      g_bins0[(size_t)BB * R2 * HID];   // 33.5 MB
__device__ unsigned      g_bins1[(size_t)BB * R2 * HID];   // 33.5 MB
__device__ float         g_cnt[BB * R2];
__device__ __nv_bfloat16 g_wh[WTOTAL];
__device__ __nv_bfloat16 g_wl[WTOTAL];

// ---------------------------------------------------------------------------
// Helpers
// ---------------------------------------------------------------------------
__device__ __forceinline__ uint32_t smem_u32(const void* p) {
    uint32_t a;
    asm("{ .reg .u64 t; cvta.to.shared.u64 t, %1; cvt.u32.u64 %0, t; }"
        : "=r"(a) : "l"(p));
    return a;
}
__device__ __forceinline__ uint32_t prmt(uint32_t a, uint32_t b, uint32_t c) {
    uint32_t d;
    asm("prmt.b32 %0, %1, %2, %3;" : "=r"(d) : "r"(a), "r"(b), "r"(c));
    return d;
}
__device__ __forceinline__ unsigned f_enc(float x) {
    unsigned u = __float_as_uint(x);
    return (u & 0x80000000u) ? ~u : (u | 0x80000000u);
}
__device__ __forceinline__ float f_dec(unsigned u) {
    return (u & 0x80000000u) ? __uint_as_float(u & 0x7FFFFFFFu) : __uint_as_float(~u);
}
// decode f_enc-coded bins value, optional relu
__device__ __forceinline__ float cvtB(uint32_t u, bool relu) {
    if (relu) return (u > 0x80000000u) ? __uint_as_float(u & 0x7FFFFFFFu) : 0.f;
    return f_dec(u);
}
// fast hi/lo split of a pair of f32 into two packed bf16x2 regs (elem a = low)
__device__ __forceinline__ void fsplit2(float a, float b, uint32_t& hp, uint32_t& lp) {
    asm("cvt.rn.bf16x2.f32 %0, %1, %2;" : "=r"(hp) : "f"(b), "f"(a));
    float ah = __uint_as_float(hp << 16);
    float bh = __uint_as_float(hp & 0xFFFF0000u);
    float ra = a - ah, rb = b - bh;
    asm("cvt.rn.bf16x2.f32 %0, %1, %2;" : "=r"(lp) : "f"(rb), "f"(ra));
}
// pack split pair (hp,lp) into per-element u32s: elem = (lo16<<16)|hi16
__device__ __forceinline__ uint2 pack2(uint32_t hp, uint32_t lp) {
    return make_uint2(prmt(hp, lp, 0x5410), prmt(hp, lp, 0x7632));
}
// ldmatrix x4 (non-trans): 4 8x8 b16 matrices, lane L supplies row addr
__device__ __forceinline__ void ldsm_x4(uint32_t& r0, uint32_t& r1,
                                        uint32_t& r2, uint32_t& r3, uint32_t addr) {
    asm volatile("ldmatrix.sync.aligned.m8n8.x4.shared.b16 {%0,%1,%2,%3}, [%4];"
                 : "=r"(r0), "=r"(r1), "=r"(r2), "=r"(r3) : "r"(addr));
}

// mma.sync m16n8k16 bf16 -> f32 accumulate
__device__ __forceinline__ void mma16816(float* d, const uint32_t* a,
                                         uint32_t b0, uint32_t b1) {
    asm volatile(
        "mma.sync.aligned.m16n8k16.row.col.f32.bf16.bf16.f32 "
        "{%0,%1,%2,%3}, {%4,%5,%6,%7}, {%8,%9}, {%0,%1,%2,%3};"
        : "+f"(d[0]), "+f"(d[1]), "+f"(d[2]), "+f"(d[3])
        : "r"(a[0]), "r"(a[1]), "r"(a[2]), "r"(a[3]), "r"(b0), "r"(b1));
}

// ---------------------------------------------------------------------------
// Weight prep: split all weights into bf16 hi/lo planes
// ---------------------------------------------------------------------------
__global__ void k_wprep(const float* __restrict__ fc0,
                        const float* __restrict__ w1,
                        const float* __restrict__ ws,
                        const float* __restrict__ fcc) {
    int t = blockIdx.x * blockDim.x + threadIdx.x;
    if (t >= WTOTAL) return;
    float v;
    if (t < 163840) {
        v = fc0[t];
    } else if (t < 409600) {
        int u = t - 163840;
        int k = u / 49152, r = u % 49152;
        int n = r / 384, c = r % 384;
        if (c < 128) v = w1[((size_t)k * HID + n) * 128 + c];
        else         v = ws[((size_t)k * HID + n) * 256 + (c - 128)];
    } else {
        v = fcc[t - 409600];
    }
    __nv_bfloat16 hi = __float2bfloat16(v);
    float lo = v - __bfloat162float(hi);
    g_wh[t] = hi;
    g_wl[t] = __float2bfloat16(lo);
}

// ---------------------------------------------------------------------------
// Zero counts only (bins zeroing is folded into k_pos / GEMM1 launches)
// g_cnt = 65536 floats = 16384 uint4 -> 64 blocks x 256 threads
// ---------------------------------------------------------------------------
__global__ void k_zc() {
    int t = blockIdx.x * blockDim.x + threadIdx.x;
    ((uint4*)g_cnt)[t] = make_uint4(0, 0, 0, 0);
}

// ---------------------------------------------------------------------------
// fc_pos + bin index + counts + initial zero of bins0/bins1 (folded)
// ---------------------------------------------------------------------------
__global__ void k_pos(const float* __restrict__ pts,
                      const float* __restrict__ w,
                      const float* __restrict__ b) {
    int m = blockIdx.x;
    int j = threadIdx.x;
    if (j < 32) {     // fold: zero 32 uint4 per buffer per block (x65536 = 33.5MB)
        uint4 z = make_uint4(0, 0, 0, 0);
        ((uint4*)g_bins0)[((size_t)m << 5) + j] = z;
        ((uint4*)g_bins1)[((size_t)m << 5) + j] = z;
    }
    float p0 = pts[(size_t)m * 3 + 0];
    float p1 = pts[(size_t)m * 3 + 1];
    float p2 = pts[(size_t)m * 3 + 2];
    float v = b[j] + p0 * w[j * 3 + 0] + p1 * w[j * 3 + 1] + p2 * w[j * 3 + 2];
    __nv_bfloat16 h = __float2bfloat16(v);
    __nv_bfloat16 l = __float2bfloat16(v - __bfloat162float(h));
    unsigned e = ((unsigned)__bfloat16_as_ushort(l) << 16) |
                 (unsigned)__bfloat16_as_ushort(h);
    g_XH[(size_t)m * LDXH + 128 + j] = e;
    if (j == 0) {
        int gx = (int)(p0 * (float)RESO);
        int gy = (int)(p1 * (float)RESO);
        gx = min(max(gx, 0), RESO - 1);
        gy = min(max(gy, 0), RESO - 1);
        int idx = gx + RESO * gy;
        g_idx[m] = idx;
        atomicAdd(&g_cnt[((m >> 14) << 14) + idx], 1.0f);
    }
}

// ---------------------------------------------------------------------------
// Fused pipelined mma.sync GEMM: C[128 x 128] per CTA = act(A) @ W^T + bias
// 8 warps (4 M x 2 N), BK=32, 3-stage cp.async pipeline, ONE barrier/chunk.
// A XOR-swizzled packed-split u32; W fragments via ldmatrix.x4.
// If zbuf != null: each CTA zeroes its 64KB slice (overlapped with K-loop).
//  mode 0: write packed-split relu(C+bias) -> XH col c_col0
//  mode 1: write packed-split (C+bias) -> XH; if binsDst scatter atomicMax(enc)
//  mode 2: scatter atomicAdd C+bias into (float*)binsDst
// ---------------------------------------------------------------------------
__global__ void __launch_bounds__(256, 2) k_gemm_mma(
    int a_col0, size_t woff, int K, int reluAll,
    const float* __restrict__ bias, int c_col0, int mode,
    const unsigned* __restrict__ binsSrc, unsigned* __restrict__ binsDst,
    int nXHc, unsigned* __restrict__ zbuf)
{
    extern __shared__ char dsm[];
    uint32_t sbase = smem_u32(dsm);
    float* bias_s = (float*)(dsm + 3 * STG);

    int tid = threadIdx.x;
    int wid = tid >> 5;
    int lid = tid & 31;
    int m0  = blockIdx.x * 128;
    int batch = m0 >> 14;
    int warp_m = wid & 3;
    int warp_n = wid >> 2;
    int g  = lid >> 2;
    int tg = lid & 3;
    int swz = (g & 3) << 3;          // A read swizzle (u32 units)

    // ldmatrix lane row mapping: m0/m1 rows 0-7, m2/m3 rows 8-15; m1/m3 = k hi
    int rip  = (lid & 7) + ((lid >> 4) << 3);
    int ksel = (lid >> 3) & 1;
    uint32_t wfrag_off = 16384 + (uint32_t)(warp_n * 64 + rip) * 80 + ksel * 16;

    if (tid < 128) bias_s[tid] = bias[tid];

    // Producer sources: 4 A segments + 4 W segments (16B each per chunk)
    uint64_t gAx[4], gAb[4], gW[4];
    uint32_t sA[4], sW[4];
    {
        #pragma unroll
        for (int i = 0; i < 4; i++) {
            int idx = tid + (i << 8);
            int row = idx >> 3, seg = idx & 7;
            gAx[i] = (uint64_t)(g_XH + (size_t)(m0 + row) * LDXH + a_col0 + seg * 4);
            sA[i]  = row * 128 + ((seg * 16) ^ ((row & 3) << 5));   // swizzled
            if (binsSrc) {
                int bi = g_idx[m0 + row];
                gAb[i] = (uint64_t)(binsSrc + (((size_t)(batch << 14) + bi) << 7) + seg * 4);
            }
        }
        #pragma unroll
        for (int i = 0; i < 4; i++) {
            int idx = tid + (i << 8);
            int pl = idx >> 9, rem = idx & 511;
            int row = rem >> 2, seg = rem & 3;
            const __nv_bfloat16* gp = pl ? g_wl : g_wh;
            gW[i] = (uint64_t)(gp + woff + (size_t)row * K + seg * 8);
            sW[i] = 16384 + pl * 10240 + row * 80 + seg * 16;
        }
    }

    auto issue = [&](int c, int s) {
        uint32_t sb = sbase + s * STG;
        bool xh = (c < nXHc);
        uint64_t advA = (uint64_t)((xh ? c : (c - nXHc)) << 7);  // 128 B/chunk
        uint64_t advW = (uint64_t)(c << 6);                       // 64 B/chunk
        #pragma unroll
        for (int i = 0; i < 4; i++) {
            uint64_t src = (xh ? gAx[i] : gAb[i]) + advA;
            asm volatile("cp.async.cg.shared.global [%0], [%1], 16;"
                         :: "r"(sb + sA[i]), "l"(src) : "memory");
        }
        #pragma unroll
        for (int i = 0; i < 4; i++)
            asm volatile("cp.async.cg.shared.global [%0], [%1], 16;"
                         :: "r"(sb + sW[i]), "l"(gW[i] + advW) : "memory");
        asm volatile("cp.async.commit_group;" ::: "memory");
    };

    float acc[2][8][4];
    #pragma unroll
    for (int mt = 0; mt < 2; mt++)
        #pragma unroll
        for (int nt = 0; nt < 8; nt++)
            #pragma unroll
            for (int r = 0; r < 4; r++) acc[mt][nt][r] = 0.f;

    const int nchunks = K >> 5;
    issue(0, 0);
    issue(1, 1);

    // Folded buffer re-zero: 64KB slice per CTA, fire-and-forget STGs that
    // retire under the K-loop. Stream order guarantees the previous reader
    // kernel finished and the next writer kernel hasn't started.
    if (zbuf) {
        uint4* zp = (uint4*)zbuf + ((size_t)blockIdx.x << 12);   // 4096 uint4/CTA
        uint4 z = make_uint4(0, 0, 0, 0);
        #pragma unroll
        for (int i = 0; i < 16; i++)
            zp[tid + (i << 8)] = z;
    }

    int s = 0;
    for (int c = 0; c < nchunks; c++) {
        if (c + 1 < nchunks) {
            asm volatile("cp.async.wait_group 1;" ::: "memory");
        } else {
            asm volatile("cp.async.wait_group 0;" ::: "memory");
        }
        __syncthreads();
        if (c + 2 < nchunks) {
            int s2 = s + 2; if (s2 >= 3) s2 -= 3;
            issue(c + 2, s2);
        }

        const char* sp = dsm + s * STG;
        const uint32_t* Au = (const uint32_t*)sp;
        uint32_t wmb = sbase + s * STG + wfrag_off;
        bool enc  = (c >= nXHc);
        bool relu = (reluAll != 0);

        #pragma unroll
        for (int ks = 0; ks < 2; ks++) {
            int col0 = (ks << 4) + (tg << 1);
            uint32_t ah[2][4], al[2][4];
            #pragma unroll
            for (int mt = 0; mt < 2; mt++) {
                int r0 = (warp_m << 5) + (mt << 4) + g;
                uint2 u0 = *(const uint2*)(Au + (r0 << 5) + (col0 ^ swz));
                uint2 u1 = *(const uint2*)(Au + ((r0 + 8) << 5) + (col0 ^ swz));
                uint2 u2 = *(const uint2*)(Au + (r0 << 5) + ((col0 + 8) ^ swz));
                uint2 u3 = *(const uint2*)(Au + ((r0 + 8) << 5) + ((col0 + 8) ^ swz));
                if (!enc) {
                    ah[mt][0] = prmt(u0.x, u0.y, 0x5410); al[mt][0] = prmt(u0.x, u0.y, 0x7632);
                    ah[mt][1] = prmt(u1.x, u1.y, 0x5410); al[mt][1] = prmt(u1.x, u1.y, 0x7632);
                    ah[mt][2] = prmt(u2.x, u2.y, 0x5410); al[mt][2] = prmt(u2.x, u2.y, 0x7632);
                    ah[mt][3] = prmt(u3.x, u3.y, 0x5410); al[mt][3] = prmt(u3.x, u3.y, 0x7632);
                    if (relu) {   // exact relu-on-split: zero halves whose hi<0
                        #pragma unroll
                        for (int r = 0; r < 4; r++) {
                            uint32_t msk = prmt(ah[mt][r], ah[mt][r], 0xBB99);
                            ah[mt][r] &= ~msk;
                            al[mt][r] &= ~msk;
                        }
                    }
                } else {
                    fsplit2(cvtB(u0.x, relu), cvtB(u0.y, relu), ah[mt][0], al[mt][0]);
                    fsplit2(cvtB(u1.x, relu), cvtB(u1.y, relu), ah[mt][1], al[mt][1]);
                    fsplit2(cvtB(u2.x, relu), cvtB(u2.y, relu), ah[mt][2], al[mt][2]);
                    fsplit2(cvtB(u3.x, relu), cvtB(u3.y, relu), ah[mt][3], al[mt][3]);
                }
            }
            #pragma unroll
            for (int p = 0; p < 4; p++) {
                uint32_t adr = wmb + p * 1280 + (ks << 5);
                uint32_t bh0a, bh1a, bh0b, bh1b, bl0a, bl1a, bl0b, bl1b;
                ldsm_x4(bh0a, bh1a, bh0b, bh1b, adr);
                ldsm_x4(bl0a, bl1a, bl0b, bl1b, adr + 10240);
                #pragma unroll
                for (int mt = 0; mt < 2; mt++) {
                    mma16816(acc[mt][2 * p], ah[mt], bh0a, bh1a);
                    mma16816(acc[mt][2 * p], ah[mt], bl0a, bl1a);
                    mma16816(acc[mt][2 * p], al[mt], bh0a, bh1a);
                    mma16816(acc[mt][2 * p + 1], ah[mt], bh0b, bh1b);
                    mma16816(acc[mt][2 * p + 1], ah[mt], bl0b, bl1b);
                    mma16816(acc[mt][2 * p + 1], al[mt], bh0b, bh1b);
                }
            }
        }
        if (++s >= 3) s -= 3;
    }

    // Epilogue rows: r_base + {0,8,16,24}
    int r_base = m0 + (warp_m << 5) + g;
    size_t bofs[4];
    if ((mode == 1 && binsDst) || mode == 2) {
        #pragma unroll
        for (int j = 0; j < 4; j++) {
            int bi = g_idx[r_base + 8 * j];
            bofs[j] = ((size_t)(batch << 14) + bi) << 7;
        }
    }

    #pragma unroll
    for (int mt = 0; mt < 2; mt++) {
        int row0 = r_base + (mt << 4);
        #pragma unroll
        for (int nt = 0; nt < 8; nt++) {
            int colL = (warp_n << 6) + (nt << 3) + (tg << 1);
            float b0 = bias_s[colL], b1 = bias_s[colL + 1];
            float v0 = acc[mt][nt][0] + b0, v1 = acc[mt][nt][1] + b1;  // row0
            float v2 = acc[mt][nt][2] + b0, v3 = acc[mt][nt][3] + b1;  // row0+8
            if (mode == 0) {
                v0 = fmaxf(v0, 0.f); v1 = fmaxf(v1, 0.f);
                v2 = fmaxf(v2, 0.f); v3 = fmaxf(v3, 0.f);
            }
            if (mode == 2) {
                float* sums = (float*)binsDst;
                atomicAdd(&sums[bofs[mt * 2 + 0] + colL],     v0);
                atomicAdd(&sums[bofs[mt * 2 + 0] + colL + 1], v1);
                atomicAdd(&sums[bofs[mt * 2 + 1] + colL],     v2);
                atomicAdd(&sums[bofs[mt * 2 + 1] + colL + 1], v3);
            } else {
                uint32_t hp, lp;
                fsplit2(v0, v1, hp, lp);
                *(uint2*)(g_XH + (size_t)row0 * LDXH + c_col0 + colL) = pack2(hp, lp);
                fsplit2(v2, v3, hp, lp);
                *(uint2*)(g_XH + (size_t)(row0 + 8) * LDXH + c_col0 + colL) = pack2(hp, lp);
                if (mode == 1 && binsDst) {
                    atomicMax(&binsDst[bofs[mt * 2 + 0] + colL],     f_enc(v0));
                    atomicMax(&binsDst[bofs[mt * 2 + 0] + colL + 1], f_enc(v1));
                    atomicMax(&binsDst[bofs[mt * 2 + 1] + colL],     f_enc(v2));
                    atomicMax(&binsDst[bofs[mt * 2 + 1] + colL + 1], f_enc(v3));
                }
            }
        }
    }
}

// ---------------------------------------------------------------------------
// Final: mean + transposed plane write (sums = bins0 as float)
// ---------------------------------------------------------------------------
__global__ void k_final(float* __restrict__ out) {
    __shared__ float s[32][33];
    __shared__ float sc[32];
    int b    = blockIdx.z;
    int bin0 = blockIdx.x * 32;
    int c0   = blockIdx.y * 32;
    const float* sums = (const float*)g_bins0;

    #pragma unroll
    for (int i = 0; i < 4; i++) {
        int binl = threadIdx.y + i * 8;
        s[binl][threadIdx.x] =
            sums[((size_t)(b * R2 + bin0 + binl)) * HID + c0 + threadIdx.x];
    }
    if (threadIdx.y == 0)
        sc[threadIdx.x] = fmaxf(g_cnt[b * R2 + bin0 + threadIdx.x], 1.0f);
    __syncthreads();

    #pragma unroll
    for (int i = 0; i < 4; i++) {
        int c = c0 + threadIdx.y + i * 8;
        out[((size_t)(b * HID + c)) * R2 + bin0 + threadIdx.x] =
            s[threadIdx.x][threadIdx.y + i * 8] / sc[threadIdx.x];
    }
}

// ---------------------------------------------------------------------------
// Launch
// ---------------------------------------------------------------------------
extern "C" void kernel_launch(void* const* d_in, const int* in_sizes, int n_in,
                              void* d_out, int out_size) {
    const float* points    = (const float*)d_in[0];
    const float* fc_pos_w  = (const float*)d_in[1];
    const float* fc_pos_b  = (const float*)d_in[2];
    const float* blk_fc0_w = (const float*)d_in[3];
    const float* blk_fc0_b = (const float*)d_in[4];
    const float* blk_fc1_w = (const float*)d_in[5];
    const float* blk_fc1_b = (const float*)d_in[6];
    const float* blk_sc_w  = (const float*)d_in[7];
    const float* fc_c_w    = (const float*)d_in[8];
    const float* fc_c_b    = (const float*)d_in[9];
    float* out = (float*)d_out;

    const int GB      = MM / 128;       // 512 GEMM blocks
    const int SMEM_SZ = 3 * STG + 512;  // 111104 B

    cudaFuncSetAttribute(k_gemm_mma, cudaFuncAttributeMaxDynamicSharedMemorySize, SMEM_SZ);

    unsigned* bins[2];
    cudaGetSymbolAddress((void**)&bins[0], g_bins0);
    cudaGetSymbolAddress((void**)&bins[1], g_bins1);

    k_wprep<<<(WTOTAL + 255) / 256, 256>>>(blk_fc0_w, blk_fc1_w, blk_sc_w, fc_c_w);
    k_zc<<<64, 256>>>();                              // FULL g_cnt zero (16384 uint4)
    k_pos<<<MM, 256>>>(points, fc_pos_w, fc_pos_b);   // also zeroes bins0/bins1

    // Block 0: H = relu(relu(x)@W0+b0) -> col 0;
    // net = [reluH | x]@Wcat + b1 -> col 128, scatter-max -> bins0
    k_gemm_mma<<<GB, 256, SMEM_SZ>>>(128, WOFF_FC0(0), 256, 1, blk_fc0_b, 0, 0,
                                     nullptr, nullptr, 8, nullptr);
    k_gemm_mma<<<GB, 256, SMEM_SZ>>>(0, WOFF_WCAT(0), 384, 0, blk_fc1_b, 128, 1,
                                     nullptr, bins[0], 12, nullptr);

    // Blocks 1..4: gather pooled from src bins; GEMM2 scatters into dst bins.
    // Re-zeroing of the buffer GEMM2(k) will write is folded into GEMM1(k).
    for (int k = 1; k < NBLK; k++) {
        const unsigned* src = bins[(k + 1) & 1];   // k:1->b0, 2->b1, 3->b0, 4->b1
        unsigned* dst = (k < 4) ? bins[k & 1] : nullptr;
        unsigned* zb  = (k >= 2) ? bins[k & 1] : nullptr;  // zero dst-of-this-k
        k_gemm_mma<<<GB, 256, SMEM_SZ>>>(128, WOFF_FC0(k), 256, 1,
                                         blk_fc0_b + k * HID, 0, 0,
                                         src, nullptr, 4, zb);
        k_gemm_mma<<<GB, 256, SMEM_SZ>>>(0, WOFF_WCAT(k), 384, 0,
                                         blk_fc1_b + k * HID, 128, 1,
                                         src, dst, 8, nullptr);
    }

    // fc_c: relu(net)@fcc + b -> scatter-add into sums (= bins0, zeroed in
    // GEMM1(k=4) since bins0's last read was as src at k=3)
    k_gemm_mma<<<GB, 256, SMEM_SZ>>>(128, WOFF_FCC, 128, 1, fc_c_b, 0, 2,
                                     nullptr, bins[0], 4, nullptr);

    dim3 fgrid(R2 / 32, HID / 32, BB);
    dim3 fblk(32, 8);
    k_final<<<fgrid, fblk>>>(out);
}